// round 1
// baseline (speedup 1.0000x reference)
#include <cuda_runtime.h>

// ---------------------------------------------------------------------------
// GraphSAGE (3 layers, mean aggregation) on GB300.
// Strategy:
//   1. Build CSR (dst-grouped edge list) once per launch:
//        histogram -> block scan -> serial block-sum scan -> offset add -> scatter
//   2. Per layer: pull-style segment-mean (one warp per node, float4 lanes)
//      then ONE fused GEMM: out = act([h | agg] @ [W_self | W_neigh]^T + b)
//      K = 256, smem-tiled SGEMM, 8x8 register blocking.
// ---------------------------------------------------------------------------

#define NN 100000
#define NE 600000
#define NB_SCAN 98   // ceil(NN / 1024)

__device__ int   g_cnt[NN];
__device__ int   g_rowptr[NN + 1];
__device__ int   g_bsum[NB_SCAN];
__device__ int   g_boff[NB_SCAN];
__device__ int   g_srcs[NE];
__device__ float g_agg[(size_t)NN * 128];
__device__ float g_h1[(size_t)NN * 128];
__device__ float g_h2[(size_t)NN * 128];

// ---------------------------- CSR construction ----------------------------

__global__ void k_zero_cnt() {
    int i = blockIdx.x * blockDim.x + threadIdx.x;
    if (i < NN) g_cnt[i] = 0;
}

__global__ void k_hist(const int* __restrict__ dst) {
    int e = blockIdx.x * blockDim.x + threadIdx.x;
    if (e < NE) atomicAdd(&g_cnt[dst[e]], 1);
}

// Block-local inclusive scan over 1024-element chunks.
__global__ void k_scan1() {
    __shared__ int sh[1024];
    int t = threadIdx.x;
    int i = blockIdx.x * 1024 + t;
    int v = (i < NN) ? g_cnt[i] : 0;
    sh[t] = v;
    __syncthreads();
#pragma unroll
    for (int off = 1; off < 1024; off <<= 1) {
        int x = (t >= off) ? sh[t - off] : 0;
        __syncthreads();
        sh[t] += x;
        __syncthreads();
    }
    if (i < NN) g_rowptr[i + 1] = sh[t];
    if (t == 1023) g_bsum[blockIdx.x] = sh[t];
}

// Exclusive scan of the 98 block sums (trivial serial).
__global__ void k_scan2() {
    if (threadIdx.x == 0 && blockIdx.x == 0) {
        int run = 0;
        for (int b = 0; b < NB_SCAN; b++) { g_boff[b] = run; run += g_bsum[b]; }
    }
}

// Add block offsets; also re-zero counters for the scatter pass.
__global__ void k_scan3() {
    int i = blockIdx.x * blockDim.x + threadIdx.x;
    if (i < NN) {
        g_rowptr[i + 1] += g_boff[i >> 10];
        g_cnt[i] = 0;
    }
    if (i == 0) g_rowptr[0] = 0;
}

__global__ void k_scatter(const int* __restrict__ src, const int* __restrict__ dst) {
    int e = blockIdx.x * blockDim.x + threadIdx.x;
    if (e < NE) {
        int d = dst[e];
        int pos = g_rowptr[d] + atomicAdd(&g_cnt[d], 1);
        g_srcs[pos] = src[e];
    }
}

// ---------------------------- segment mean (pull) -------------------------
// One warp per destination node. 128 feats = one float4 per lane.

__global__ void k_agg(const float* __restrict__ h, float* __restrict__ agg) {
    int gw   = (blockIdx.x * blockDim.x + threadIdx.x) >> 5;
    int lane = threadIdx.x & 31;
    if (gw >= NN) return;
    int s = g_rowptr[gw];
    int e = g_rowptr[gw + 1];
    float4 acc = make_float4(0.f, 0.f, 0.f, 0.f);
    for (int j = s; j < e; j++) {
        int sc = g_srcs[j];
        float4 v = *(const float4*)(h + (size_t)sc * 128 + lane * 4);
        acc.x += v.x; acc.y += v.y; acc.z += v.z; acc.w += v.w;
    }
    float inv = 1.0f / (float)max(e - s, 1);
    acc.x *= inv; acc.y *= inv; acc.z *= inv; acc.w *= inv;
    *(float4*)(agg + (size_t)gw * 128 + lane * 4) = acc;
}

// ---------------------------- fused concat GEMM ---------------------------
// out[M, DOUT] = act( hin @ Ws^T + agg @ Wn^T + b )
// A = [hin | agg] (K = 256), B column k<128 from Ws, k>=128 from Wn.
// Tile: BM=128, BN=DOUT, BK=16, thread tile 8x8.

template <int DOUT, bool RELU>
__global__ void __launch_bounds__((128 / 8) * (DOUT / 8))
k_gemm(const float* __restrict__ hin,
       const float* __restrict__ agg,
       const float* __restrict__ Ws,
       const float* __restrict__ Wn,
       const float* __restrict__ bias,
       float* __restrict__ out) {
    constexpr int DIN = 128, KK = 256, BK = 16, BM = 128, BN = DOUT;
    constexpr int TM = 8, TN = 8;
    constexpr int NTH = (BM / TM) * (BN / TN);

    __shared__ float As[BK][BM];
    __shared__ float Bs[BK][BN];

    const int tid  = threadIdx.x;
    const int row0 = blockIdx.x * BM;
    const int tm0  = (tid / (BN / TN)) * TM;
    const int tn0  = (tid % (BN / TN)) * TN;

    float acc[TM][TN];
#pragma unroll
    for (int i = 0; i < TM; i++)
#pragma unroll
        for (int j = 0; j < TN; j++) acc[i][j] = 0.f;

#pragma unroll
    for (int kt = 0; kt < KK / BK; kt++) {
        const int k0 = kt * BK;
        const float* Ap  = (k0 < DIN) ? hin : agg;
        const float* Wp  = (k0 < DIN) ? Ws  : Wn;
        const int   koff = (k0 < DIN) ? k0  : (k0 - DIN);

        // Load A tile (transposed into smem), guarded on M.
        constexpr int A4 = BM * BK / 4;
        constexpr int AP = A4 / NTH;
#pragma unroll
        for (int it = 0; it < AP; it++) {
            int j  = tid + it * NTH;
            int m  = j / (BK / 4);
            int k4 = j % (BK / 4);
            int r  = row0 + m;
            float4 v = make_float4(0.f, 0.f, 0.f, 0.f);
            if (r < NN) v = *(const float4*)(Ap + (size_t)r * DIN + koff + k4 * 4);
            As[k4 * 4 + 0][m] = v.x;
            As[k4 * 4 + 1][m] = v.y;
            As[k4 * 4 + 2][m] = v.z;
            As[k4 * 4 + 3][m] = v.w;
        }
        // Load B tile: Bs[k][n] = W[n][koff+k]
        constexpr int B4 = BN * BK / 4;
        constexpr int BP = B4 / NTH;
#pragma unroll
        for (int it = 0; it < BP; it++) {
            int j  = tid + it * NTH;
            int n  = j / (BK / 4);
            int k4 = j % (BK / 4);
            float4 v = *(const float4*)(Wp + (size_t)n * DIN + koff + k4 * 4);
            Bs[k4 * 4 + 0][n] = v.x;
            Bs[k4 * 4 + 1][n] = v.y;
            Bs[k4 * 4 + 2][n] = v.z;
            Bs[k4 * 4 + 3][n] = v.w;
        }
        __syncthreads();

#pragma unroll
        for (int k = 0; k < BK; k++) {
            float4 a0 = *(const float4*)&As[k][tm0];
            float4 a1 = *(const float4*)&As[k][tm0 + 4];
            float4 b0 = *(const float4*)&Bs[k][tn0];
            float4 b1 = *(const float4*)&Bs[k][tn0 + 4];
            float ra[8] = {a0.x, a0.y, a0.z, a0.w, a1.x, a1.y, a1.z, a1.w};
            float rb[8] = {b0.x, b0.y, b0.z, b0.w, b1.x, b1.y, b1.z, b1.w};
#pragma unroll
            for (int i = 0; i < TM; i++)
#pragma unroll
                for (int jj = 0; jj < TN; jj++)
                    acc[i][jj] += ra[i] * rb[jj];
        }
        __syncthreads();
    }

    // Epilogue: bias, optional relu, guarded float4 stores.
#pragma unroll
    for (int i = 0; i < TM; i++) {
        int r = row0 + tm0 + i;
        if (r >= NN) continue;
#pragma unroll
        for (int j = 0; j < TN; j += 4) {
            float4 v;
            v.x = acc[i][j + 0] + __ldg(&bias[tn0 + j + 0]);
            v.y = acc[i][j + 1] + __ldg(&bias[tn0 + j + 1]);
            v.z = acc[i][j + 2] + __ldg(&bias[tn0 + j + 2]);
            v.w = acc[i][j + 3] + __ldg(&bias[tn0 + j + 3]);
            if (RELU) {
                v.x = fmaxf(v.x, 0.f); v.y = fmaxf(v.y, 0.f);
                v.z = fmaxf(v.z, 0.f); v.w = fmaxf(v.w, 0.f);
            }
            *(float4*)(out + (size_t)r * DOUT + tn0 + j) = v;
        }
    }
}

// ---------------------------------------------------------------------------

extern "C" void kernel_launch(void* const* d_in, const int* in_sizes, int n_in,
                              void* d_out, int out_size) {
    const float* x    = (const float*)d_in[0];
    const int*   esrc = (const int*)  d_in[1];
    const int*   edst = (const int*)  d_in[2];
    const float* Ws1  = (const float*)d_in[3];
    const float* Wn1  = (const float*)d_in[4];
    const float* b1   = (const float*)d_in[5];
    const float* Ws2  = (const float*)d_in[6];
    const float* Wn2  = (const float*)d_in[7];
    const float* b2   = (const float*)d_in[8];
    const float* Ws3  = (const float*)d_in[9];
    const float* Wn3  = (const float*)d_in[10];
    const float* b3   = (const float*)d_in[11];
    float* out = (float*)d_out;

    float *agg, *h1, *h2;
    cudaGetSymbolAddress((void**)&agg, g_agg);
    cudaGetSymbolAddress((void**)&h1,  g_h1);
    cudaGetSymbolAddress((void**)&h2,  g_h2);

    const int TB = 256;
    const int gridN = (NN + TB - 1) / TB;
    const int gridE = (NE + TB - 1) / TB;
    const int gridW = (NN * 32 + TB - 1) / TB;   // one warp per node
    const int gridM = (NN + 127) / 128;

    // CSR build
    k_zero_cnt<<<gridN, TB>>>();
    k_hist<<<gridE, TB>>>(edst);
    k_scan1<<<NB_SCAN, 1024>>>();
    k_scan2<<<1, 32>>>();
    k_scan3<<<gridN, TB>>>();
    k_scatter<<<gridE, TB>>>(esrc, edst);

    // Layer 1
    k_agg<<<gridW, TB>>>(x, agg);
    k_gemm<128, true><<<gridM, 256>>>(x, agg, Ws1, Wn1, b1, h1);

    // Layer 2
    k_agg<<<gridW, TB>>>(h1, agg);
    k_gemm<128, true><<<gridM, 256>>>(h1, agg, Ws2, Wn2, b2, h2);

    // Layer 3 (no relu, writes d_out)
    k_agg<<<gridW, TB>>>(h2, agg);
    k_gemm<64, false><<<gridM, 128>>>(h2, agg, Ws3, Wn3, b3, out);
}

// round 4
// speedup vs baseline: 1.9302x; 1.9302x over previous
#include <cuda_runtime.h>
#include <cuda_bf16.h>
#include <cstdint>

// ---------------------------------------------------------------------------
// GraphSAGE (3 layers, mean agg) on GB300 — mma.sync (HMMA) split-bf16 GEMM.
//   CSR build -> per layer: warp-gather segment-mean (split-bf16 I/O)
//   -> fused K=256 GEMM: out = act([h | agg] @ [Ws | Wn]^T + b)
//   fp32 accuracy via 3-term split: AhiBhi + AloBhi + AhiBlo.
// R4 fix: B fragments use non-transposed ldmatrix (W[n][k] IS the col-major
// B layout for mma.row.col; the addressing was already non-trans form).
// ---------------------------------------------------------------------------

#define NN 100000
#define NE 600000
#define NB_SCAN 98

// CSR scratch
__device__ int g_cnt[NN];
__device__ int g_rowptr[NN + 1];
__device__ int g_bsum[NB_SCAN];
__device__ int g_srcs[NE];

// activations as split bf16 (hi + lo ~= fp32)
__device__ __nv_bfloat16 g_s0hi[(size_t)NN * 128];
__device__ __nv_bfloat16 g_s0lo[(size_t)NN * 128];
__device__ __nv_bfloat16 g_s1hi[(size_t)NN * 128];
__device__ __nv_bfloat16 g_s1lo[(size_t)NN * 128];
__device__ __nv_bfloat16 g_agghi[(size_t)NN * 128];
__device__ __nv_bfloat16 g_agglo[(size_t)NN * 128];

// weights split bf16, packed: Ws1,Wn1,Ws2,Wn2,Ws3,Wn3
#define WS1 0
#define WN1 16384
#define WS2 32768
#define WN2 49152
#define WS3 65536
#define WN3 73728
#define NWE 81920
__device__ __nv_bfloat16 g_whi[NWE];
__device__ __nv_bfloat16 g_wlo[NWE];

// ---------------------------- PTX helpers ---------------------------------

__device__ __forceinline__ uint32_t smem_u32(const void* p) {
    uint32_t a;
    asm("{ .reg .u64 t; cvta.to.shared.u64 t, %1; cvt.u32.u64 %0, t; }" : "=r"(a) : "l"(p));
    return a;
}
__device__ __forceinline__ void ldsm_x4(uint32_t* r, uint32_t addr) {
    asm volatile("ldmatrix.sync.aligned.m8n8.x4.shared.b16 {%0,%1,%2,%3}, [%4];"
                 : "=r"(r[0]), "=r"(r[1]), "=r"(r[2]), "=r"(r[3]) : "r"(addr));
}
__device__ __forceinline__ void mma_bf16(float* d, const uint32_t* a, const uint32_t* b) {
    asm volatile(
        "mma.sync.aligned.m16n8k16.row.col.f32.bf16.bf16.f32 "
        "{%0,%1,%2,%3}, {%4,%5,%6,%7}, {%8,%9}, {%0,%1,%2,%3};"
        : "+f"(d[0]), "+f"(d[1]), "+f"(d[2]), "+f"(d[3])
        : "r"(a[0]), "r"(a[1]), "r"(a[2]), "r"(a[3]), "r"(b[0]), "r"(b[1]));
}

// ---------------------------- CSR construction ----------------------------

__global__ void k_zero_cnt() {
    int i = blockIdx.x * blockDim.x + threadIdx.x;
    if (i < NN) g_cnt[i] = 0;
}
__global__ void k_hist(const int* __restrict__ dst) {
    int e = blockIdx.x * blockDim.x + threadIdx.x;
    if (e < NE) atomicAdd(&g_cnt[dst[e]], 1);
}
__global__ void k_scan1() {
    __shared__ int sh[1024];
    int t = threadIdx.x;
    int i = blockIdx.x * 1024 + t;
    int v = (i < NN) ? g_cnt[i] : 0;
    sh[t] = v;
    __syncthreads();
#pragma unroll
    for (int off = 1; off < 1024; off <<= 1) {
        int x = (t >= off) ? sh[t - off] : 0;
        __syncthreads();
        sh[t] += x;
        __syncthreads();
    }
    if (i < NN) g_rowptr[i + 1] = sh[t];
    if (t == 1023) g_bsum[blockIdx.x] = sh[t];
}
__global__ void k_scan2() {
    __shared__ int sh[128];
    int t = threadIdx.x;
    int v = (t < NB_SCAN) ? g_bsum[t] : 0;
    sh[t] = v;
    __syncthreads();
#pragma unroll
    for (int off = 1; off < 128; off <<= 1) {
        int x = (t >= off) ? sh[t - off] : 0;
        __syncthreads();
        sh[t] += x;
        __syncthreads();
    }
    if (t < NB_SCAN) g_bsum[t] = sh[t] - v;  // exclusive
}
__global__ void k_scan3() {
    int i = blockIdx.x * blockDim.x + threadIdx.x;
    if (i < NN) {
        g_rowptr[i + 1] += g_bsum[i >> 10];
        g_cnt[i] = 0;
    }
    if (i == 0) g_rowptr[0] = 0;
}
__global__ void k_scatter(const int* __restrict__ src, const int* __restrict__ dst) {
    int e = blockIdx.x * blockDim.x + threadIdx.x;
    if (e < NE) {
        int d = dst[e];
        int pos = g_rowptr[d] + atomicAdd(&g_cnt[d], 1);
        g_srcs[pos] = src[e];
    }
}

// ---------------------------- conversions ---------------------------------

__device__ __forceinline__ void split1(float v, __nv_bfloat16& h, __nv_bfloat16& l) {
    h = __float2bfloat16_rn(v);
    l = __float2bfloat16_rn(v - __bfloat162float(h));
}
__device__ __forceinline__ uint32_t pack2(__nv_bfloat16 a, __nv_bfloat16 b) {
    __nv_bfloat162 t;
    t.x = a; t.y = b;
    return *reinterpret_cast<uint32_t*>(&t);
}

__global__ void k_conv_x(const float* __restrict__ x) {
    size_t i = (size_t)blockIdx.x * blockDim.x + threadIdx.x;  // float4 index
    if (i >= (size_t)NN * 32) return;
    float4 v = *(const float4*)(x + i * 4);
    __nv_bfloat16 h0, h1, h2, h3, l0, l1, l2, l3;
    split1(v.x, h0, l0); split1(v.y, h1, l1); split1(v.z, h2, l2); split1(v.w, h3, l3);
    *(uint2*)(g_s0hi + i * 4) = make_uint2(pack2(h0, h1), pack2(h2, h3));
    *(uint2*)(g_s0lo + i * 4) = make_uint2(pack2(l0, l1), pack2(l2, l3));
}

__global__ void k_conv_w(const float* __restrict__ ws1, const float* __restrict__ wn1,
                         const float* __restrict__ ws2, const float* __restrict__ wn2,
                         const float* __restrict__ ws3, const float* __restrict__ wn3) {
    int i = blockIdx.x * blockDim.x + threadIdx.x;  // float4 index
    int e = i * 4;
    if (e >= NWE) return;
    const float* src; int base;
    if      (e < WN1) { src = ws1; base = WS1; }
    else if (e < WS2) { src = wn1; base = WN1; }
    else if (e < WN2) { src = ws2; base = WS2; }
    else if (e < WS3) { src = wn2; base = WN2; }
    else if (e < WN3) { src = ws3; base = WS3; }
    else              { src = wn3; base = WN3; }
    float4 v = *(const float4*)(src + (e - base));
    __nv_bfloat16 h0, h1, h2, h3, l0, l1, l2, l3;
    split1(v.x, h0, l0); split1(v.y, h1, l1); split1(v.z, h2, l2); split1(v.w, h3, l3);
    *(uint2*)(g_whi + e) = make_uint2(pack2(h0, h1), pack2(h2, h3));
    *(uint2*)(g_wlo + e) = make_uint2(pack2(l0, l1), pack2(l2, l3));
}

// ---------------------------- segment mean --------------------------------

template <bool SPLIT_SRC>
__global__ void k_agg(const float* __restrict__ hf,
                      const __nv_bfloat16* __restrict__ hhi,
                      const __nv_bfloat16* __restrict__ hlo,
                      __nv_bfloat16* __restrict__ ahi,
                      __nv_bfloat16* __restrict__ alo) {
    int gw = (blockIdx.x * blockDim.x + threadIdx.x) >> 5;
    int lane = threadIdx.x & 31;
    if (gw >= NN) return;
    int s = g_rowptr[gw];
    int e = g_rowptr[gw + 1];
    float a0 = 0.f, a1 = 0.f, a2 = 0.f, a3 = 0.f;
    for (int j = s; j < e; j++) {
        size_t off = ((size_t)g_srcs[j] << 7) + lane * 4;
        if (SPLIT_SRC) {
            uint2 vh = *(const uint2*)(hhi + off);
            uint2 vl = *(const uint2*)(hlo + off);
            float2 h01 = __bfloat1622float2(*reinterpret_cast<__nv_bfloat162*>(&vh.x));
            float2 h23 = __bfloat1622float2(*reinterpret_cast<__nv_bfloat162*>(&vh.y));
            float2 l01 = __bfloat1622float2(*reinterpret_cast<__nv_bfloat162*>(&vl.x));
            float2 l23 = __bfloat1622float2(*reinterpret_cast<__nv_bfloat162*>(&vl.y));
            a0 += h01.x + l01.x; a1 += h01.y + l01.y;
            a2 += h23.x + l23.x; a3 += h23.y + l23.y;
        } else {
            float4 v = *(const float4*)(hf + off);
            a0 += v.x; a1 += v.y; a2 += v.z; a3 += v.w;
        }
    }
    float inv = 1.0f / (float)max(e - s, 1);
    a0 *= inv; a1 *= inv; a2 *= inv; a3 *= inv;
    __nv_bfloat16 h0, h1, h2, h3, l0, l1, l2, l3;
    split1(a0, h0, l0); split1(a1, h1, l1); split1(a2, h2, l2); split1(a3, h3, l3);
    size_t o = ((size_t)gw << 7) + lane * 4;
    *(uint2*)(ahi + o) = make_uint2(pack2(h0, h1), pack2(h2, h3));
    *(uint2*)(alo + o) = make_uint2(pack2(l0, l1), pack2(l2, l3));
}

// ---------------------------- HMMA GEMM -----------------------------------
// Block: 128 rows x DOUT cols, 8 warps (wm=wid&3 -> 32 rows, wn=wid>>2 -> DOUT/2 cols).
// K=256 processed as 4 chunks of 64 (chunks 0-1: self/Ws, 2-3: agg/Wn).
// SMEM tiles row-major with 128B rows, XOR-8 swizzled 16B chunks.

template <int DOUT, bool RELU, bool SPLIT_OUT>
__global__ void __launch_bounds__(256)
k_gemm_mma(const __nv_bfloat16* __restrict__ ahi, const __nv_bfloat16* __restrict__ alo,
           const __nv_bfloat16* __restrict__ ghi, const __nv_bfloat16* __restrict__ glo,
           const __nv_bfloat16* __restrict__ wshi, const __nv_bfloat16* __restrict__ wslo,
           const __nv_bfloat16* __restrict__ wnhi, const __nv_bfloat16* __restrict__ wnlo,
           const float* __restrict__ bias,
           float* __restrict__ outf,
           __nv_bfloat16* __restrict__ ohi, __nv_bfloat16* __restrict__ olo) {
    extern __shared__ char sm[];
    constexpr int A_H = 0, A_L = 16384, B_H = 32768, B_L = 32768 + DOUT * 128;
    constexpr int WARP_N = DOUT / 2;
    constexpr int NT = WARP_N / 8;  // n-tiles per warp: 8 (DOUT=128) or 4 (DOUT=64)

    const int tid = threadIdx.x, wid = tid >> 5, lane = tid & 31;
    const int wm = wid & 3, wn = wid >> 2;
    const int row0 = blockIdx.x * 128;
    const uint32_t sb = smem_u32(sm);

    float acc[2][NT][4];
#pragma unroll
    for (int mt = 0; mt < 2; mt++)
#pragma unroll
        for (int nt = 0; nt < NT; nt++)
#pragma unroll
            for (int q = 0; q < 4; q++) acc[mt][nt][q] = 0.f;

#pragma unroll
    for (int c = 0; c < 4; c++) {
        const __nv_bfloat16* Ah = (c < 2) ? ahi : ghi;
        const __nv_bfloat16* Al = (c < 2) ? alo : glo;
        const __nv_bfloat16* Bh = (c < 2) ? wshi : wnhi;
        const __nv_bfloat16* Bl = (c < 2) ? wslo : wnlo;
        const int koff = (c & 1) * 64;

        if (c) __syncthreads();  // previous chunk's compute done before overwrite

        // A tiles: 128 rows x 8 x 16B chunks (hi + lo)
#pragma unroll
        for (int it = 0; it < 4; it++) {
            int ch = it * 256 + tid;
            int r = ch >> 3, kc = ch & 7;
            uint32_t dst = (uint32_t)(r * 128) + (uint32_t)((kc ^ (r & 7)) << 4);
            uint4 vh = make_uint4(0u, 0u, 0u, 0u), vl = vh;
            if (row0 + r < NN) {
                size_t off = ((size_t)(row0 + r) << 7) + koff + (kc << 3);
                vh = *(const uint4*)(Ah + off);
                vl = *(const uint4*)(Al + off);
            }
            *(uint4*)(sm + A_H + dst) = vh;
            *(uint4*)(sm + A_L + dst) = vl;
        }
        // B tiles: DOUT rows x 8 chunks
#pragma unroll
        for (int it = 0; it < DOUT * 8 / 256; it++) {
            int ch = it * 256 + tid;
            int r = ch >> 3, kc = ch & 7;
            uint32_t dst = (uint32_t)(r * 128) + (uint32_t)((kc ^ (r & 7)) << 4);
            size_t off = ((size_t)r << 7) + koff + (kc << 3);
            *(uint4*)(sm + B_H + dst) = *(const uint4*)(Bh + off);
            *(uint4*)(sm + B_L + dst) = *(const uint4*)(Bl + off);
        }
        __syncthreads();

#pragma unroll
        for (int ks = 0; ks < 4; ks++) {
            uint32_t ahf[2][4], alf[2][4];
#pragma unroll
            for (int mt = 0; mt < 2; mt++) {
                int r = wm * 32 + mt * 16 + (lane & 15);
                int kc = ks * 2 + (lane >> 4);
                uint32_t o = (uint32_t)(r * 128) + (uint32_t)((kc ^ (r & 7)) << 4);
                ldsm_x4(ahf[mt], sb + A_H + o);
                ldsm_x4(alf[mt], sb + A_L + o);
            }
            uint32_t bhf[NT][2], blf[NT][2];
#pragma unroll
            for (int np = 0; np < NT / 2; np++) {
                // non-trans ldmatrix: lanes 0-7 -> n0-7/k-lo, 8-15 -> n0-7/k-hi,
                // 16-23 -> n8-15/k-lo, 24-31 -> n8-15/k-hi
                int n = wn * WARP_N + np * 16 + (lane & 7) + ((lane >> 4) << 3);
                int kc = ks * 2 + ((lane >> 3) & 1);
                uint32_t o = (uint32_t)(n * 128) + (uint32_t)((kc ^ (n & 7)) << 4);
                uint32_t t4[4];
                ldsm_x4(t4, sb + B_H + o);
                bhf[np * 2][0] = t4[0]; bhf[np * 2][1] = t4[1];
                bhf[np * 2 + 1][0] = t4[2]; bhf[np * 2 + 1][1] = t4[3];
                ldsm_x4(t4, sb + B_L + o);
                blf[np * 2][0] = t4[0]; blf[np * 2][1] = t4[1];
                blf[np * 2 + 1][0] = t4[2]; blf[np * 2 + 1][1] = t4[3];
            }
#pragma unroll
            for (int mt = 0; mt < 2; mt++)
#pragma unroll
                for (int nt = 0; nt < NT; nt++) {
                    mma_bf16(acc[mt][nt], ahf[mt], bhf[nt]);
                    mma_bf16(acc[mt][nt], alf[mt], bhf[nt]);
                    mma_bf16(acc[mt][nt], ahf[mt], blf[nt]);
                }
        }
    }

    // Epilogue. D frag: lane g=l>>2,t=l&3: {D[g][2t],D[g][2t+1],D[g+8][2t],D[g+8][2t+1]}
    const int g = lane >> 2, t = lane & 3;
#pragma unroll
    for (int mt = 0; mt < 2; mt++) {
        int r0 = row0 + wm * 32 + mt * 16 + g;
        int r1 = r0 + 8;
#pragma unroll
        for (int nt = 0; nt < NT; nt++) {
            int col = wn * WARP_N + nt * 8 + 2 * t;
            float b0 = __ldg(bias + col), b1 = __ldg(bias + col + 1);
            float c0 = acc[mt][nt][0] + b0, c1 = acc[mt][nt][1] + b1;
            float c2 = acc[mt][nt][2] + b0, c3 = acc[mt][nt][3] + b1;
            if (RELU) {
                c0 = fmaxf(c0, 0.f); c1 = fmaxf(c1, 0.f);
                c2 = fmaxf(c2, 0.f); c3 = fmaxf(c3, 0.f);
            }
            if (SPLIT_OUT) {
                __nv_bfloat16 h0, h1, l0, l1;
                if (r0 < NN) {
                    split1(c0, h0, l0); split1(c1, h1, l1);
                    size_t o = ((size_t)r0 << 7) + col;
                    *(uint32_t*)(ohi + o) = pack2(h0, h1);
                    *(uint32_t*)(olo + o) = pack2(l0, l1);
                }
                if (r1 < NN) {
                    split1(c2, h0, l0); split1(c3, h1, l1);
                    size_t o = ((size_t)r1 << 7) + col;
                    *(uint32_t*)(ohi + o) = pack2(h0, h1);
                    *(uint32_t*)(olo + o) = pack2(l0, l1);
                }
            } else {
                if (r0 < NN) *(float2*)(outf + (size_t)r0 * DOUT + col) = make_float2(c0, c1);
                if (r1 < NN) *(float2*)(outf + (size_t)r1 * DOUT + col) = make_float2(c2, c3);
            }
        }
    }
}

// ---------------------------------------------------------------------------

extern "C" void kernel_launch(void* const* d_in, const int* in_sizes, int n_in,
                              void* d_out, int out_size) {
    const float* x   = (const float*)d_in[0];
    const int* esrc  = (const int*)d_in[1];
    const int* edst  = (const int*)d_in[2];
    const float* Ws1 = (const float*)d_in[3];
    const float* Wn1 = (const float*)d_in[4];
    const float* b1  = (const float*)d_in[5];
    const float* Ws2 = (const float*)d_in[6];
    const float* Wn2 = (const float*)d_in[7];
    const float* b2  = (const float*)d_in[8];
    const float* Ws3 = (const float*)d_in[9];
    const float* Wn3 = (const float*)d_in[10];
    const float* b3  = (const float*)d_in[11];
    float* out = (float*)d_out;

    __nv_bfloat16 *s0hi, *s0lo, *s1hi, *s1lo, *aghi, *aglo, *whi, *wlo;
    cudaGetSymbolAddress((void**)&s0hi, g_s0hi);
    cudaGetSymbolAddress((void**)&s0lo, g_s0lo);
    cudaGetSymbolAddress((void**)&s1hi, g_s1hi);
    cudaGetSymbolAddress((void**)&s1lo, g_s1lo);
    cudaGetSymbolAddress((void**)&aghi, g_agghi);
    cudaGetSymbolAddress((void**)&aglo, g_agglo);
    cudaGetSymbolAddress((void**)&whi, g_whi);
    cudaGetSymbolAddress((void**)&wlo, g_wlo);

    const int SMEM128 = 65536;  // A 32K + B 32K
    const int SMEM64  = 49152;  // A 32K + B 16K
    cudaFuncSetAttribute(k_gemm_mma<128, true, true>,
                         cudaFuncAttributeMaxDynamicSharedMemorySize, SMEM128);
    cudaFuncSetAttribute(k_gemm_mma<64, false, false>,
                         cudaFuncAttributeMaxDynamicSharedMemorySize, SMEM64);

    const int TB = 256;
    const int gridN = (NN + TB - 1) / TB;
    const int gridE = (NE + TB - 1) / TB;
    const int gridW = (NN * 32 + TB - 1) / TB;
    const int gridM = (NN + 127) / 128;  // 782

    // CSR build
    k_zero_cnt<<<gridN, TB>>>();
    k_hist<<<gridE, TB>>>(edst);
    k_scan1<<<NB_SCAN, 1024>>>();
    k_scan2<<<1, 128>>>();
    k_scan3<<<gridN, TB>>>();
    k_scatter<<<gridE, TB>>>(esrc, edst);

    // conversions
    k_conv_x<<<(NN * 32 + TB - 1) / TB, TB>>>(x);
    k_conv_w<<<(NWE / 4 + 127) / 128, 128>>>(Ws1, Wn1, Ws2, Wn2, Ws3, Wn3);

    // Layer 1
    k_agg<false><<<gridW, TB>>>(x, nullptr, nullptr, aghi, aglo);
    k_gemm_mma<128, true, true><<<gridM, 256, SMEM128>>>(
        s0hi, s0lo, aghi, aglo,
        whi + WS1, wlo + WS1, whi + WN1, wlo + WN1, b1,
        nullptr, s1hi, s1lo);

    // Layer 2
    k_agg<true><<<gridW, TB>>>(nullptr, s1hi, s1lo, aghi, aglo);
    k_gemm_mma<128, true, true><<<gridM, 256, SMEM128>>>(
        s1hi, s1lo, aghi, aglo,
        whi + WS2, wlo + WS2, whi + WN2, wlo + WN2, b2,
        nullptr, s0hi, s0lo);

    // Layer 3 (fp32 out)
    k_agg<true><<<gridW, TB>>>(nullptr, s0hi, s0lo, aghi, aglo);
    k_gemm_mma<64, false, false><<<gridM, 256, SMEM64>>>(
        s0hi, s0lo, aghi, aglo,
        whi + WS3, wlo + WS3, whi + WN3, wlo + WN3, b3,
        out, nullptr, nullptr);
}

// round 5
// speedup vs baseline: 2.0017x; 1.0370x over previous
#include <cuda_runtime.h>
#include <cuda_bf16.h>
#include <cstdint>

// ---------------------------------------------------------------------------
// GraphSAGE (3 layers, mean agg) on GB300 — HMMA split-bf16, cp.async pipeline.
//   CSR build -> per layer: warp-gather segment-mean (split-bf16 I/O)
//   -> fused K=256 GEMM (8 stages of K=32, double-buffered cp.async):
//      out = act([h | agg] @ [Ws | Wn]^T + b), 3-term split for fp32 accuracy.
// R5: conv_x removed (layer-1 GEMM splits fp32 x inline); 80B-stride tiles
// (conflict-free ldmatrix, no XOR swizzle); LDGSTS overlap with MMA.
// ---------------------------------------------------------------------------

#define NN 100000
#define NE 600000
#define NB_SCAN 98

// CSR scratch
__device__ int g_cnt[NN];
__device__ int g_rowptr[NN + 1];
__device__ int g_bsum[NB_SCAN];
__device__ int g_srcs[NE];

// activations as split bf16 (hi + lo ~= fp32)
__device__ __nv_bfloat16 g_s0hi[(size_t)NN * 128];
__device__ __nv_bfloat16 g_s0lo[(size_t)NN * 128];
__device__ __nv_bfloat16 g_s1hi[(size_t)NN * 128];
__device__ __nv_bfloat16 g_s1lo[(size_t)NN * 128];
__device__ __nv_bfloat16 g_agghi[(size_t)NN * 128];
__device__ __nv_bfloat16 g_agglo[(size_t)NN * 128];

// weights split bf16, packed: Ws1,Wn1,Ws2,Wn2,Ws3,Wn3
#define WS1 0
#define WN1 16384
#define WS2 32768
#define WN2 49152
#define WS3 65536
#define WN3 73728
#define NWE 81920
__device__ __nv_bfloat16 g_whi[NWE];
__device__ __nv_bfloat16 g_wlo[NWE];

// ---------------------------- PTX helpers ---------------------------------

__device__ __forceinline__ uint32_t smem_u32(const void* p) {
    uint32_t a;
    asm("{ .reg .u64 t; cvta.to.shared.u64 t, %1; cvt.u32.u64 %0, t; }" : "=r"(a) : "l"(p));
    return a;
}
__device__ __forceinline__ void ldsm_x4(uint32_t* r, uint32_t addr) {
    asm volatile("ldmatrix.sync.aligned.m8n8.x4.shared.b16 {%0,%1,%2,%3}, [%4];"
                 : "=r"(r[0]), "=r"(r[1]), "=r"(r[2]), "=r"(r[3]) : "r"(addr));
}
__device__ __forceinline__ void mma_bf16(float* d, const uint32_t* a, const uint32_t* b) {
    asm volatile(
        "mma.sync.aligned.m16n8k16.row.col.f32.bf16.bf16.f32 "
        "{%0,%1,%2,%3}, {%4,%5,%6,%7}, {%8,%9}, {%0,%1,%2,%3};"
        : "+f"(d[0]), "+f"(d[1]), "+f"(d[2]), "+f"(d[3])
        : "r"(a[0]), "r"(a[1]), "r"(a[2]), "r"(a[3]), "r"(b[0]), "r"(b[1]));
}
__device__ __forceinline__ void cp16(uint32_t dst, const void* src, bool valid) {
    int sz = valid ? 16 : 0;
    asm volatile("cp.async.cg.shared.global [%0], [%1], 16, %2;"
                 :: "r"(dst), "l"(src), "r"(sz) : "memory");
}
#define CP_COMMIT() asm volatile("cp.async.commit_group;" ::: "memory")
#define CP_WAIT0()  asm volatile("cp.async.wait_group 0;" ::: "memory")

// ---------------------------- CSR construction ----------------------------

__global__ void k_zero_cnt() {
    int i = blockIdx.x * blockDim.x + threadIdx.x;
    if (i < NN) g_cnt[i] = 0;
}
__global__ void k_hist(const int* __restrict__ dst) {
    int e = blockIdx.x * blockDim.x + threadIdx.x;
    if (e < NE) atomicAdd(&g_cnt[dst[e]], 1);
}
__global__ void k_scan1() {
    __shared__ int sh[1024];
    int t = threadIdx.x;
    int i = blockIdx.x * 1024 + t;
    int v = (i < NN) ? g_cnt[i] : 0;
    sh[t] = v;
    __syncthreads();
#pragma unroll
    for (int off = 1; off < 1024; off <<= 1) {
        int x = (t >= off) ? sh[t - off] : 0;
        __syncthreads();
        sh[t] += x;
        __syncthreads();
    }
    if (i < NN) g_rowptr[i + 1] = sh[t];
    if (t == 1023) g_bsum[blockIdx.x] = sh[t];
}
__global__ void k_scan2() {
    __shared__ int sh[128];
    int t = threadIdx.x;
    int v = (t < NB_SCAN) ? g_bsum[t] : 0;
    sh[t] = v;
    __syncthreads();
#pragma unroll
    for (int off = 1; off < 128; off <<= 1) {
        int x = (t >= off) ? sh[t - off] : 0;
        __syncthreads();
        sh[t] += x;
        __syncthreads();
    }
    if (t < NB_SCAN) g_bsum[t] = sh[t] - v;  // exclusive
}
__global__ void k_scan3() {
    int i = blockIdx.x * blockDim.x + threadIdx.x;
    if (i < NN) {
        g_rowptr[i + 1] += g_bsum[i >> 10];
        g_cnt[i] = 0;
    }
    if (i == 0) g_rowptr[0] = 0;
}
__global__ void k_scatter(const int* __restrict__ src, const int* __restrict__ dst) {
    int e = blockIdx.x * blockDim.x + threadIdx.x;
    if (e < NE) {
        int d = dst[e];
        int pos = g_rowptr[d] + atomicAdd(&g_cnt[d], 1);
        g_srcs[pos] = src[e];
    }
}

// ---------------------------- conversions ---------------------------------

__device__ __forceinline__ void split1(float v, __nv_bfloat16& h, __nv_bfloat16& l) {
    h = __float2bfloat16_rn(v);
    l = __float2bfloat16_rn(v - __bfloat162float(h));
}
__device__ __forceinline__ uint32_t pack2(__nv_bfloat16 a, __nv_bfloat16 b) {
    __nv_bfloat162 t;
    t.x = a; t.y = b;
    return *reinterpret_cast<uint32_t*>(&t);
}

__global__ void k_conv_w(const float* __restrict__ ws1, const float* __restrict__ wn1,
                         const float* __restrict__ ws2, const float* __restrict__ wn2,
                         const float* __restrict__ ws3, const float* __restrict__ wn3) {
    int i = blockIdx.x * blockDim.x + threadIdx.x;  // float4 index
    int e = i * 4;
    if (e >= NWE) return;
    const float* src; int base;
    if      (e < WN1) { src = ws1; base = WS1; }
    else if (e < WS2) { src = wn1; base = WN1; }
    else if (e < WN2) { src = ws2; base = WS2; }
    else if (e < WS3) { src = wn2; base = WN2; }
    else if (e < WN3) { src = ws3; base = WS3; }
    else              { src = wn3; base = WN3; }
    float4 v = *(const float4*)(src + (e - base));
    __nv_bfloat16 h0, h1, h2, h3, l0, l1, l2, l3;
    split1(v.x, h0, l0); split1(v.y, h1, l1); split1(v.z, h2, l2); split1(v.w, h3, l3);
    *(uint2*)(g_whi + e) = make_uint2(pack2(h0, h1), pack2(h2, h3));
    *(uint2*)(g_wlo + e) = make_uint2(pack2(l0, l1), pack2(l2, l3));
}

// ---------------------------- segment mean --------------------------------

template <bool SPLIT_SRC>
__global__ void k_agg(const float* __restrict__ hf,
                      const __nv_bfloat16* __restrict__ hhi,
                      const __nv_bfloat16* __restrict__ hlo,
                      __nv_bfloat16* __restrict__ ahi,
                      __nv_bfloat16* __restrict__ alo) {
    int gw = (blockIdx.x * blockDim.x + threadIdx.x) >> 5;
    int lane = threadIdx.x & 31;
    if (gw >= NN) return;
    int s = g_rowptr[gw];
    int e = g_rowptr[gw + 1];
    float a0 = 0.f, a1 = 0.f, a2 = 0.f, a3 = 0.f;
    for (int j = s; j < e; j++) {
        size_t off = ((size_t)g_srcs[j] << 7) + lane * 4;
        if (SPLIT_SRC) {
            uint2 vh = *(const uint2*)(hhi + off);
            uint2 vl = *(const uint2*)(hlo + off);
            float2 h01 = __bfloat1622float2(*reinterpret_cast<__nv_bfloat162*>(&vh.x));
            float2 h23 = __bfloat1622float2(*reinterpret_cast<__nv_bfloat162*>(&vh.y));
            float2 l01 = __bfloat1622float2(*reinterpret_cast<__nv_bfloat162*>(&vl.x));
            float2 l23 = __bfloat1622float2(*reinterpret_cast<__nv_bfloat162*>(&vl.y));
            a0 += h01.x + l01.x; a1 += h01.y + l01.y;
            a2 += h23.x + l23.x; a3 += h23.y + l23.y;
        } else {
            float4 v = *(const float4*)(hf + off);
            a0 += v.x; a1 += v.y; a2 += v.z; a3 += v.w;
        }
    }
    float inv = 1.0f / (float)max(e - s, 1);
    a0 *= inv; a1 *= inv; a2 *= inv; a3 *= inv;
    __nv_bfloat16 h0, h1, h2, h3, l0, l1, l2, l3;
    split1(a0, h0, l0); split1(a1, h1, l1); split1(a2, h2, l2); split1(a3, h3, l3);
    size_t o = ((size_t)gw << 7) + lane * 4;
    *(uint2*)(ahi + o) = make_uint2(pack2(h0, h1), pack2(h2, h3));
    *(uint2*)(alo + o) = make_uint2(pack2(l0, l1), pack2(l2, l3));
}

// ---------------------------- HMMA GEMM -----------------------------------
// 128 x DOUT block, 8 warps. K=256 as 8 stages of K=32 (stages 0-3: self/Ws,
// 4-7: agg/Wn), double-buffered cp.async. Tiles use 80B row stride: r*80 mod
// 128 cycles all eight 16B banks over 8 rows -> conflict-free ldmatrix.
// SPLIT_A: self operand is fp32 (layer 1): LDG->regs overlapped, split->STS.

template <int DOUT, bool RELU, bool SPLIT_OUT, bool SPLIT_A>
__global__ void __launch_bounds__(256)
k_gemm_mma(const float* __restrict__ xf,
           const __nv_bfloat16* __restrict__ ahi, const __nv_bfloat16* __restrict__ alo,
           const __nv_bfloat16* __restrict__ ghi, const __nv_bfloat16* __restrict__ glo,
           const __nv_bfloat16* __restrict__ wshi, const __nv_bfloat16* __restrict__ wslo,
           const __nv_bfloat16* __restrict__ wnhi, const __nv_bfloat16* __restrict__ wnlo,
           const float* __restrict__ bias,
           float* __restrict__ outf,
           __nv_bfloat16* __restrict__ ohi, __nv_bfloat16* __restrict__ olo) {
    extern __shared__ char sm[];
    constexpr int A_B = 128 * 80;        // one A tile (hi or lo)
    constexpr int B_B = DOUT * 80;
    constexpr int STG = 2 * A_B + 2 * B_B;
    constexpr int WARP_N = DOUT / 2;
    constexpr int NT = WARP_N / 8;

    const int tid = threadIdx.x, wid = tid >> 5, lane = tid & 31;
    const int wm = wid & 3, wn = wid >> 2;
    const int row0 = blockIdx.x * 128;
    const uint32_t sb = smem_u32(sm);

    float acc[2][NT][4];
#pragma unroll
    for (int mt = 0; mt < 2; mt++)
#pragma unroll
        for (int nt = 0; nt < NT; nt++)
#pragma unroll
            for (int q = 0; q < 4; q++) acc[mt][nt][q] = 0.f;

    float xr[SPLIT_A ? 16 : 1];

    // ---- loaders ----
    auto loadB = [&](int s, int p) {
        const int koff = (s & 3) * 32;
        const __nv_bfloat16* Bh = (s < 4) ? wshi : wnhi;
        const __nv_bfloat16* Bl = (s < 4) ? wslo : wnlo;
        const uint32_t bh = sb + p * STG + 2 * A_B, bl = bh + B_B;
#pragma unroll
        for (int i = 0; i < DOUT * 4 / 256; i++) {
            int c = i * 256 + tid;
            int r = c >> 2, kc = c & 3;
            size_t off = ((size_t)r << 7) + koff + kc * 8;
            cp16(bh + r * 80 + kc * 16, Bh + off, true);
            cp16(bl + r * 80 + kc * 16, Bl + off, true);
        }
    };
    auto loadA_cp = [&](int s, int p) {
        const int koff = (s & 3) * 32;
        const __nv_bfloat16* Ah = (s < 4) ? ahi : ghi;
        const __nv_bfloat16* Al = (s < 4) ? alo : glo;
        const uint32_t ah = sb + p * STG, al = ah + A_B;
#pragma unroll
        for (int i = 0; i < 2; i++) {
            int c = i * 256 + tid;
            int r = c >> 2, kc = c & 3;
            bool v = (row0 + r) < NN;
            size_t off = ((size_t)(row0 + r) << 7) + koff + kc * 8;
            cp16(ah + r * 80 + kc * 16, Ah + off, v);
            cp16(al + r * 80 + kc * 16, Al + off, v);
        }
    };
    auto ldgA = [&](int s) {
        const int koff = (s & 3) * 32;
#pragma unroll
        for (int i = 0; i < 4; i++) {
            int c = i * 256 + tid;
            int r = c >> 3, q = c & 7;
            float4 t = make_float4(0.f, 0.f, 0.f, 0.f);
            if (row0 + r < NN)
                t = *(const float4*)(xf + ((size_t)(row0 + r) << 7) + koff + q * 4);
            xr[i * 4 + 0] = t.x; xr[i * 4 + 1] = t.y;
            xr[i * 4 + 2] = t.z; xr[i * 4 + 3] = t.w;
        }
    };
    auto stsA = [&](int p) {
        const uint32_t ah = sb + p * STG, al = ah + A_B;
#pragma unroll
        for (int i = 0; i < 4; i++) {
            int c = i * 256 + tid;
            int r = c >> 3, q = c & 7;
            __nv_bfloat16 h0, h1, h2, h3, l0, l1, l2, l3;
            split1(xr[i * 4 + 0], h0, l0); split1(xr[i * 4 + 1], h1, l1);
            split1(xr[i * 4 + 2], h2, l2); split1(xr[i * 4 + 3], h3, l3);
            uint32_t hh0 = pack2(h0, h1), hh1 = pack2(h2, h3);
            uint32_t ll0 = pack2(l0, l1), ll1 = pack2(l2, l3);
            uint32_t d = r * 80 + q * 8;
            asm volatile("st.shared.v2.b32 [%0], {%1,%2};" :: "r"(ah + d), "r"(hh0), "r"(hh1) : "memory");
            asm volatile("st.shared.v2.b32 [%0], {%1,%2};" :: "r"(al + d), "r"(ll0), "r"(ll1) : "memory");
        }
    };
    auto compute = [&](int p) {
#pragma unroll
        for (int ks = 0; ks < 2; ks++) {
            uint32_t ahf[2][4], alf[2][4];
#pragma unroll
            for (int mt = 0; mt < 2; mt++) {
                int r = wm * 32 + mt * 16 + (lane & 15);
                int kc = ks * 2 + (lane >> 4);
                uint32_t o = p * STG + (uint32_t)(r * 80) + (uint32_t)(kc * 16);
                ldsm_x4(ahf[mt], sb + o);
                ldsm_x4(alf[mt], sb + A_B + o);
            }
            uint32_t bhf[NT][2], blf[NT][2];
#pragma unroll
            for (int np = 0; np < NT / 2; np++) {
                int n = wn * WARP_N + np * 16 + (lane & 7) + ((lane >> 4) << 3);
                int kc = ks * 2 + ((lane >> 3) & 1);
                uint32_t o = p * STG + 2 * A_B + (uint32_t)(n * 80) + (uint32_t)(kc * 16);
                uint32_t t4[4];
                ldsm_x4(t4, sb + o);
                bhf[np * 2][0] = t4[0]; bhf[np * 2][1] = t4[1];
                bhf[np * 2 + 1][0] = t4[2]; bhf[np * 2 + 1][1] = t4[3];
                ldsm_x4(t4, sb + B_B + o);
                blf[np * 2][0] = t4[0]; blf[np * 2][1] = t4[1];
                blf[np * 2 + 1][0] = t4[2]; blf[np * 2 + 1][1] = t4[3];
            }
#pragma unroll
            for (int mt = 0; mt < 2; mt++)
#pragma unroll
                for (int nt = 0; nt < NT; nt++) {
                    mma_bf16(acc[mt][nt], ahf[mt], bhf[nt]);
                    mma_bf16(acc[mt][nt], alf[mt], bhf[nt]);
                    mma_bf16(acc[mt][nt], ahf[mt], blf[nt]);
                }
        }
    };

    // ---- prologue: stage 0 ----
    loadB(0, 0);
    if (SPLIT_A) { ldgA(0); stsA(0); }
    else loadA_cp(0, 0);
    CP_COMMIT();
    CP_WAIT0();
    __syncthreads();

    // ---- pipelined mainloop ----
    int p = 0;
#pragma unroll
    for (int s = 0; s < 8; s++) {
        const int sn = s + 1;
        if (sn < 8) {
            loadB(sn, p ^ 1);
            if (SPLIT_A && sn < 4) ldgA(sn);
            else loadA_cp(sn, p ^ 1);
            CP_COMMIT();
        }
        compute(p);
        if (sn < 8) {
            if (SPLIT_A && sn < 4) stsA(p ^ 1);
            CP_WAIT0();
            __syncthreads();
            p ^= 1;
        }
    }

    // ---- epilogue ----
    const int g = lane >> 2, t = lane & 3;
#pragma unroll
    for (int mt = 0; mt < 2; mt++) {
        int r0 = row0 + wm * 32 + mt * 16 + g;
        int r1 = r0 + 8;
#pragma unroll
        for (int nt = 0; nt < NT; nt++) {
            int col = wn * WARP_N + nt * 8 + 2 * t;
            float b0 = __ldg(bias + col), b1 = __ldg(bias + col + 1);
            float c0 = acc[mt][nt][0] + b0, c1 = acc[mt][nt][1] + b1;
            float c2 = acc[mt][nt][2] + b0, c3 = acc[mt][nt][3] + b1;
            if (RELU) {
                c0 = fmaxf(c0, 0.f); c1 = fmaxf(c1, 0.f);
                c2 = fmaxf(c2, 0.f); c3 = fmaxf(c3, 0.f);
            }
            if (SPLIT_OUT) {
                __nv_bfloat16 h0, h1, l0, l1;
                if (r0 < NN) {
                    split1(c0, h0, l0); split1(c1, h1, l1);
                    size_t o = ((size_t)r0 << 7) + col;
                    *(uint32_t*)(ohi + o) = pack2(h0, h1);
                    *(uint32_t*)(olo + o) = pack2(l0, l1);
                }
                if (r1 < NN) {
                    split1(c2, h0, l0); split1(c3, h1, l1);
                    size_t o = ((size_t)r1 << 7) + col;
                    *(uint32_t*)(ohi + o) = pack2(h0, h1);
                    *(uint32_t*)(olo + o) = pack2(l0, l1);
                }
            } else {
                if (r0 < NN) *(float2*)(outf + (size_t)r0 * DOUT + col) = make_float2(c0, c1);
                if (r1 < NN) *(float2*)(outf + (size_t)r1 * DOUT + col) = make_float2(c2, c3);
            }
        }
    }
}

// ---------------------------------------------------------------------------

extern "C" void kernel_launch(void* const* d_in, const int* in_sizes, int n_in,
                              void* d_out, int out_size) {
    const float* x   = (const float*)d_in[0];
    const int* esrc  = (const int*)d_in[1];
    const int* edst  = (const int*)d_in[2];
    const float* Ws1 = (const float*)d_in[3];
    const float* Wn1 = (const float*)d_in[4];
    const float* b1  = (const float*)d_in[5];
    const float* Ws2 = (const float*)d_in[6];
    const float* Wn2 = (const float*)d_in[7];
    const float* b2  = (const float*)d_in[8];
    const float* Ws3 = (const float*)d_in[9];
    const float* Wn3 = (const float*)d_in[10];
    const float* b3  = (const float*)d_in[11];
    float* out = (float*)d_out;

    __nv_bfloat16 *s0hi, *s0lo, *s1hi, *s1lo, *aghi, *aglo, *whi, *wlo;
    cudaGetSymbolAddress((void**)&s0hi, g_s0hi);
    cudaGetSymbolAddress((void**)&s0lo, g_s0lo);
    cudaGetSymbolAddress((void**)&s1hi, g_s1hi);
    cudaGetSymbolAddress((void**)&s1lo, g_s1lo);
    cudaGetSymbolAddress((void**)&aghi, g_agghi);
    cudaGetSymbolAddress((void**)&aglo, g_agglo);
    cudaGetSymbolAddress((void**)&whi, g_whi);
    cudaGetSymbolAddress((void**)&wlo, g_wlo);

    // smem: 2 stages * (2*A + 2*B) with 80B row stride
    const int SMEM128 = 2 * (2 * 128 * 80 + 2 * 128 * 80);  // 81920
    const int SMEM64  = 2 * (2 * 128 * 80 + 2 * 64 * 80);   // 61440
    cudaFuncSetAttribute(k_gemm_mma<128, true, true, true>,
                         cudaFuncAttributeMaxDynamicSharedMemorySize, SMEM128);
    cudaFuncSetAttribute(k_gemm_mma<128, true, true, false>,
                         cudaFuncAttributeMaxDynamicSharedMemorySize, SMEM128);
    cudaFuncSetAttribute(k_gemm_mma<64, false, false, false>,
                         cudaFuncAttributeMaxDynamicSharedMemorySize, SMEM64);

    const int TB = 256;
    const int gridN = (NN + TB - 1) / TB;
    const int gridE = (NE + TB - 1) / TB;
    const int gridW = (NN * 32 + TB - 1) / TB;
    const int gridM = (NN + 127) / 128;  // 782

    // CSR build
    k_zero_cnt<<<gridN, TB>>>();
    k_hist<<<gridE, TB>>>(edst);
    k_scan1<<<NB_SCAN, 1024>>>();
    k_scan2<<<1, 128>>>();
    k_scan3<<<gridN, TB>>>();
    k_scatter<<<gridE, TB>>>(esrc, edst);

    // weights split (tiny)
    k_conv_w<<<(NWE / 4 + 127) / 128, 128>>>(Ws1, Wn1, Ws2, Wn2, Ws3, Wn3);

    // Layer 1: agg from fp32 x; self path splits x inline (SPLIT_A)
    k_agg<false><<<gridW, TB>>>(x, nullptr, nullptr, aghi, aglo);
    k_gemm_mma<128, true, true, true><<<gridM, 256, SMEM128>>>(
        x, nullptr, nullptr, aghi, aglo,
        whi + WS1, wlo + WS1, whi + WN1, wlo + WN1, b1,
        nullptr, s1hi, s1lo);

    // Layer 2
    k_agg<true><<<gridW, TB>>>(nullptr, s1hi, s1lo, aghi, aglo);
    k_gemm_mma<128, true, true, false><<<gridM, 256, SMEM128>>>(
        nullptr, s1hi, s1lo, aghi, aglo,
        whi + WS2, wlo + WS2, whi + WN2, wlo + WN2, b2,
        nullptr, s0hi, s0lo);

    // Layer 3 (fp32 out)
    k_agg<true><<<gridW, TB>>>(nullptr, s0hi, s0lo, aghi, aglo);
    k_gemm_mma<64, false, false, false><<<gridM, 256, SMEM64>>>(
        nullptr, s0hi, s0lo, aghi, aglo,
        whi + WS3, wlo + WS3, whi + WN3, wlo + WN3, b3,
        out, nullptr, nullptr);
}

// round 6
// speedup vs baseline: 2.0233x; 1.0108x over previous
#include <cuda_runtime.h>
#include <cuda_bf16.h>
#include <cstdint>

// ---------------------------------------------------------------------------
// GraphSAGE (3 layers, mean agg) on GB300 — HMMA split-bf16 + fast CSR.
// R6: single-pass decoupled-lookback scan (3 kernels -> 1); agg uses
// half-warp hi/lo lane split (16B loads, shfl combine, edge unroll x2).
// ---------------------------------------------------------------------------

#define NN 100000
#define NE 600000
#define NB_SCAN 98

// CSR scratch
__device__ int g_cnt[NN];
__device__ int g_rowptr[NN + 1];
__device__ unsigned long long g_state[NB_SCAN];
__device__ int g_srcs[NE];

// activations as split bf16 (hi + lo ~= fp32)
__device__ __align__(128) __nv_bfloat16 g_s0hi[(size_t)NN * 128];
__device__ __align__(128) __nv_bfloat16 g_s0lo[(size_t)NN * 128];
__device__ __align__(128) __nv_bfloat16 g_s1hi[(size_t)NN * 128];
__device__ __align__(128) __nv_bfloat16 g_s1lo[(size_t)NN * 128];
__device__ __align__(128) __nv_bfloat16 g_agghi[(size_t)NN * 128];
__device__ __align__(128) __nv_bfloat16 g_agglo[(size_t)NN * 128];

// weights split bf16, packed: Ws1,Wn1,Ws2,Wn2,Ws3,Wn3
#define WS1 0
#define WN1 16384
#define WS2 32768
#define WN2 49152
#define WS3 65536
#define WN3 73728
#define NWE 81920
__device__ __align__(128) __nv_bfloat16 g_whi[NWE];
__device__ __align__(128) __nv_bfloat16 g_wlo[NWE];

// ---------------------------- PTX helpers ---------------------------------

__device__ __forceinline__ uint32_t smem_u32(const void* p) {
    uint32_t a;
    asm("{ .reg .u64 t; cvta.to.shared.u64 t, %1; cvt.u32.u64 %0, t; }" : "=r"(a) : "l"(p));
    return a;
}
__device__ __forceinline__ void ldsm_x4(uint32_t* r, uint32_t addr) {
    asm volatile("ldmatrix.sync.aligned.m8n8.x4.shared.b16 {%0,%1,%2,%3}, [%4];"
                 : "=r"(r[0]), "=r"(r[1]), "=r"(r[2]), "=r"(r[3]) : "r"(addr));
}
__device__ __forceinline__ void mma_bf16(float* d, const uint32_t* a, const uint32_t* b) {
    asm volatile(
        "mma.sync.aligned.m16n8k16.row.col.f32.bf16.bf16.f32 "
        "{%0,%1,%2,%3}, {%4,%5,%6,%7}, {%8,%9}, {%0,%1,%2,%3};"
        : "+f"(d[0]), "+f"(d[1]), "+f"(d[2]), "+f"(d[3])
        : "r"(a[0]), "r"(a[1]), "r"(a[2]), "r"(a[3]), "r"(b[0]), "r"(b[1]));
}
__device__ __forceinline__ void cp16(uint32_t dst, const void* src, bool valid) {
    int sz = valid ? 16 : 0;
    asm volatile("cp.async.cg.shared.global [%0], [%1], 16, %2;"
                 :: "r"(dst), "l"(src), "r"(sz) : "memory");
}
#define CP_COMMIT() asm volatile("cp.async.commit_group;" ::: "memory")
#define CP_WAIT0()  asm volatile("cp.async.wait_group 0;" ::: "memory")

// ---------------------------- CSR construction ----------------------------

__global__ void k_zero() {
    int i = blockIdx.x * blockDim.x + threadIdx.x;
    if (i < NN) g_cnt[i] = 0;
    if (i < NB_SCAN) g_state[i] = 0ULL;
}
__global__ void k_hist(const int* __restrict__ dst) {
    int e = blockIdx.x * blockDim.x + threadIdx.x;
    if (e < NE) atomicAdd(&g_cnt[dst[e]], 1);
}

// Single-pass scan: block-local inclusive scan + decoupled lookback (sum of
// all predecessor aggregates; flag in high 32 bits). All 98 blocks co-resident.
__global__ void k_scan() {
    __shared__ int sh[1024];
    __shared__ int s_prefix;
    const int t = threadIdx.x, b = blockIdx.x;
    const int i = b * 1024 + t;
    int v = (i < NN) ? g_cnt[i] : 0;
    sh[t] = v;
    __syncthreads();
#pragma unroll
    for (int off = 1; off < 1024; off <<= 1) {
        int x = (t >= off) ? sh[t - off] : 0;
        __syncthreads();
        sh[t] += x;
        __syncthreads();
    }
    if (t == 1023)
        atomicExch(&g_state[b], (1ULL << 32) | (unsigned)sh[1023]);
    if (t < 32) {
        int run = 0;
        for (int base = b - 1; base >= 0; base -= 32) {
            int idx = base - t;
            unsigned val = 0;
            if (idx >= 0) {
                unsigned long long w;
                do { w = atomicAdd(&g_state[idx], 0ULL); } while ((w >> 32) == 0);
                val = (unsigned)w;
            }
#pragma unroll
            for (int o = 16; o; o >>= 1) val += __shfl_xor_sync(0xffffffffu, val, o);
            run += (int)val;
        }
        if (t == 0) s_prefix = run;
    }
    __syncthreads();
    int prefix = s_prefix;
    if (i < NN) {
        g_rowptr[i + 1] = prefix + sh[t];
        g_cnt[i] = 0;  // re-zero for scatter
    }
    if (i == 0) g_rowptr[0] = 0;
}

__global__ void k_scatter(const int* __restrict__ src, const int* __restrict__ dst) {
    int e = blockIdx.x * blockDim.x + threadIdx.x;
    if (e < NE) {
        int d = dst[e];
        int pos = g_rowptr[d] + atomicAdd(&g_cnt[d], 1);
        g_srcs[pos] = src[e];
    }
}

// ---------------------------- conversions ---------------------------------

__device__ __forceinline__ void split1(float v, __nv_bfloat16& h, __nv_bfloat16& l) {
    h = __float2bfloat16_rn(v);
    l = __float2bfloat16_rn(v - __bfloat162float(h));
}
__device__ __forceinline__ uint32_t pack2(__nv_bfloat16 a, __nv_bfloat16 b) {
    __nv_bfloat162 t;
    t.x = a; t.y = b;
    return *reinterpret_cast<uint32_t*>(&t);
}
__device__ __forceinline__ float2 upk(uint32_t w) {
    return __bfloat1622float2(*reinterpret_cast<__nv_bfloat162*>(&w));
}

__global__ void k_conv_w(const float* __restrict__ ws1, const float* __restrict__ wn1,
                         const float* __restrict__ ws2, const float* __restrict__ wn2,
                         const float* __restrict__ ws3, const float* __restrict__ wn3) {
    int i = blockIdx.x * blockDim.x + threadIdx.x;  // float4 index
    int e = i * 4;
    if (e >= NWE) return;
    const float* src; int base;
    if      (e < WN1) { src = ws1; base = WS1; }
    else if (e < WS2) { src = wn1; base = WN1; }
    else if (e < WN2) { src = ws2; base = WS2; }
    else if (e < WS3) { src = wn2; base = WN2; }
    else if (e < WN3) { src = ws3; base = WS3; }
    else              { src = wn3; base = WN3; }
    float4 v = *(const float4*)(src + (e - base));
    __nv_bfloat16 h0, h1, h2, h3, l0, l1, l2, l3;
    split1(v.x, h0, l0); split1(v.y, h1, l1); split1(v.z, h2, l2); split1(v.w, h3, l3);
    *(uint2*)(g_whi + e) = make_uint2(pack2(h0, h1), pack2(h2, h3));
    *(uint2*)(g_wlo + e) = make_uint2(pack2(l0, l1), pack2(l2, l3));
}

// ---------------------------- segment mean --------------------------------
// One warp per node. Split path: lanes 0-15 gather hi, lanes 16-31 gather lo
// (same 8 feats each), one 16B LDG per lane per edge, shfl-combine at end.

__global__ void k_agg_split(const __nv_bfloat16* __restrict__ hhi,
                            const __nv_bfloat16* __restrict__ hlo,
                            __nv_bfloat16* __restrict__ ahi,
                            __nv_bfloat16* __restrict__ alo) {
    int gw = (blockIdx.x * blockDim.x + threadIdx.x) >> 5;
    int lane = threadIdx.x & 31;
    if (gw >= NN) return;
    const int s = g_rowptr[gw];
    const int e = g_rowptr[gw + 1];
    const __nv_bfloat16* base = (lane < 16) ? hhi : hlo;
    const int f0 = (lane & 15) * 8;
    float a[8];
#pragma unroll
    for (int q = 0; q < 8; q++) a[q] = 0.f;
    int j = s;
    for (; j + 1 < e; j += 2) {
        int s0 = g_srcs[j], s1 = g_srcs[j + 1];
        uint4 v0 = *(const uint4*)(base + (((size_t)s0) << 7) + f0);
        uint4 v1 = *(const uint4*)(base + (((size_t)s1) << 7) + f0);
        float2 p;
        p = upk(v0.x); a[0] += p.x; a[1] += p.y;
        p = upk(v0.y); a[2] += p.x; a[3] += p.y;
        p = upk(v0.z); a[4] += p.x; a[5] += p.y;
        p = upk(v0.w); a[6] += p.x; a[7] += p.y;
        p = upk(v1.x); a[0] += p.x; a[1] += p.y;
        p = upk(v1.y); a[2] += p.x; a[3] += p.y;
        p = upk(v1.z); a[4] += p.x; a[5] += p.y;
        p = upk(v1.w); a[6] += p.x; a[7] += p.y;
    }
    if (j < e) {
        uint4 v0 = *(const uint4*)(base + (((size_t)g_srcs[j]) << 7) + f0);
        float2 p;
        p = upk(v0.x); a[0] += p.x; a[1] += p.y;
        p = upk(v0.y); a[2] += p.x; a[3] += p.y;
        p = upk(v0.z); a[4] += p.x; a[5] += p.y;
        p = upk(v0.w); a[6] += p.x; a[7] += p.y;
    }
#pragma unroll
    for (int q = 0; q < 8; q++) a[q] += __shfl_xor_sync(0xffffffffu, a[q], 16);
    if (lane < 16) {
        float inv = 1.0f / (float)max(e - s, 1);
        __nv_bfloat16 h[8], l[8];
#pragma unroll
        for (int q = 0; q < 8; q++) split1(a[q] * inv, h[q], l[q]);
        size_t o = (((size_t)gw) << 7) + f0;
        *(uint4*)(ahi + o) = make_uint4(pack2(h[0], h[1]), pack2(h[2], h[3]),
                                        pack2(h[4], h[5]), pack2(h[6], h[7]));
        *(uint4*)(alo + o) = make_uint4(pack2(l[0], l[1]), pack2(l[2], l[3]),
                                        pack2(l[4], l[5]), pack2(l[6], l[7]));
    }
}

// Layer-1 variant: gather fp32 x (4 feats/lane), edge unroll x2.
__global__ void k_agg_f32(const float* __restrict__ hf,
                          __nv_bfloat16* __restrict__ ahi,
                          __nv_bfloat16* __restrict__ alo) {
    int gw = (blockIdx.x * blockDim.x + threadIdx.x) >> 5;
    int lane = threadIdx.x & 31;
    if (gw >= NN) return;
    const int s = g_rowptr[gw];
    const int e = g_rowptr[gw + 1];
    float a0 = 0.f, a1 = 0.f, a2 = 0.f, a3 = 0.f;
    int j = s;
    for (; j + 1 < e; j += 2) {
        int s0 = g_srcs[j], s1 = g_srcs[j + 1];
        float4 v0 = *(const float4*)(hf + (((size_t)s0) << 7) + lane * 4);
        float4 v1 = *(const float4*)(hf + (((size_t)s1) << 7) + lane * 4);
        a0 += v0.x + v1.x; a1 += v0.y + v1.y;
        a2 += v0.z + v1.z; a3 += v0.w + v1.w;
    }
    if (j < e) {
        float4 v = *(const float4*)(hf + (((size_t)g_srcs[j]) << 7) + lane * 4);
        a0 += v.x; a1 += v.y; a2 += v.z; a3 += v.w;
    }
    float inv = 1.0f / (float)max(e - s, 1);
    a0 *= inv; a1 *= inv; a2 *= inv; a3 *= inv;
    __nv_bfloat16 h0, h1, h2, h3, l0, l1, l2, l3;
    split1(a0, h0, l0); split1(a1, h1, l1); split1(a2, h2, l2); split1(a3, h3, l3);
    size_t o = (((size_t)gw) << 7) + lane * 4;
    *(uint2*)(ahi + o) = make_uint2(pack2(h0, h1), pack2(h2, h3));
    *(uint2*)(alo + o) = make_uint2(pack2(l0, l1), pack2(l2, l3));
}

// ---------------------------- HMMA GEMM -----------------------------------
// 128 x DOUT block, 8 warps. K=256 as 8 stages of K=32 (stages 0-3: self/Ws,
// 4-7: agg/Wn), double-buffered cp.async. 80B-stride rows (conflict-free).
// SPLIT_A: self operand is fp32 (layer 1): LDG->regs overlapped, split->STS.

template <int DOUT, bool RELU, bool SPLIT_OUT, bool SPLIT_A>
__global__ void __launch_bounds__(256)
k_gemm_mma(const float* __restrict__ xf,
           const __nv_bfloat16* __restrict__ ahi, const __nv_bfloat16* __restrict__ alo,
           const __nv_bfloat16* __restrict__ ghi, const __nv_bfloat16* __restrict__ glo,
           const __nv_bfloat16* __restrict__ wshi, const __nv_bfloat16* __restrict__ wslo,
           const __nv_bfloat16* __restrict__ wnhi, const __nv_bfloat16* __restrict__ wnlo,
           const float* __restrict__ bias,
           float* __restrict__ outf,
           __nv_bfloat16* __restrict__ ohi, __nv_bfloat16* __restrict__ olo) {
    extern __shared__ char sm[];
    constexpr int A_B = 128 * 80;
    constexpr int B_B = DOUT * 80;
    constexpr int STG = 2 * A_B + 2 * B_B;
    constexpr int WARP_N = DOUT / 2;
    constexpr int NT = WARP_N / 8;

    const int tid = threadIdx.x, wid = tid >> 5, lane = tid & 31;
    const int wm = wid & 3, wn = wid >> 2;
    const int row0 = blockIdx.x * 128;
    const uint32_t sb = smem_u32(sm);

    float acc[2][NT][4];
#pragma unroll
    for (int mt = 0; mt < 2; mt++)
#pragma unroll
        for (int nt = 0; nt < NT; nt++)
#pragma unroll
            for (int q = 0; q < 4; q++) acc[mt][nt][q] = 0.f;

    float xr[SPLIT_A ? 16 : 1];

    auto loadB = [&](int s, int p) {
        const int koff = (s & 3) * 32;
        const __nv_bfloat16* Bh = (s < 4) ? wshi : wnhi;
        const __nv_bfloat16* Bl = (s < 4) ? wslo : wnlo;
        const uint32_t bh = sb + p * STG + 2 * A_B, bl = bh + B_B;
#pragma unroll
        for (int i = 0; i < DOUT * 4 / 256; i++) {
            int c = i * 256 + tid;
            int r = c >> 2, kc = c & 3;
            size_t off = ((size_t)r << 7) + koff + kc * 8;
            cp16(bh + r * 80 + kc * 16, Bh + off, true);
            cp16(bl + r * 80 + kc * 16, Bl + off, true);
        }
    };
    auto loadA_cp = [&](int s, int p) {
        const int koff = (s & 3) * 32;
        const __nv_bfloat16* Ah = (s < 4) ? ahi : ghi;
        const __nv_bfloat16* Al = (s < 4) ? alo : glo;
        const uint32_t ah = sb + p * STG, al = ah + A_B;
#pragma unroll
        for (int i = 0; i < 2; i++) {
            int c = i * 256 + tid;
            int r = c >> 2, kc = c & 3;
            bool v = (row0 + r) < NN;
            size_t off = ((size_t)(row0 + r) << 7) + koff + kc * 8;
            cp16(ah + r * 80 + kc * 16, Ah + off, v);
            cp16(al + r * 80 + kc * 16, Al + off, v);
        }
    };
    auto ldgA = [&](int s) {
        const int koff = (s & 3) * 32;
#pragma unroll
        for (int i = 0; i < 4; i++) {
            int c = i * 256 + tid;
            int r = c >> 3, q = c & 7;
            float4 t = make_float4(0.f, 0.f, 0.f, 0.f);
            if (row0 + r < NN)
                t = *(const float4*)(xf + ((size_t)(row0 + r) << 7) + koff + q * 4);
            xr[i * 4 + 0] = t.x; xr[i * 4 + 1] = t.y;
            xr[i * 4 + 2] = t.z; xr[i * 4 + 3] = t.w;
        }
    };
    auto stsA = [&](int p) {
        const uint32_t ah = sb + p * STG, al = ah + A_B;
#pragma unroll
        for (int i = 0; i < 4; i++) {
            int c = i * 256 + tid;
            int r = c >> 3, q = c & 7;
            __nv_bfloat16 h0, h1, h2, h3, l0, l1, l2, l3;
            split1(xr[i * 4 + 0], h0, l0); split1(xr[i * 4 + 1], h1, l1);
            split1(xr[i * 4 + 2], h2, l2); split1(xr[i * 4 + 3], h3, l3);
            uint32_t hh0 = pack2(h0, h1), hh1 = pack2(h2, h3);
            uint32_t ll0 = pack2(l0, l1), ll1 = pack2(l2, l3);
            uint32_t d = r * 80 + q * 8;
            asm volatile("st.shared.v2.b32 [%0], {%1,%2};" :: "r"(ah + d), "r"(hh0), "r"(hh1) : "memory");
            asm volatile("st.shared.v2.b32 [%0], {%1,%2};" :: "r"(al + d), "r"(ll0), "r"(ll1) : "memory");
        }
    };
    auto compute = [&](int p) {
#pragma unroll
        for (int ks = 0; ks < 2; ks++) {
            uint32_t ahf[2][4], alf[2][4];
#pragma unroll
            for (int mt = 0; mt < 2; mt++) {
                int r = wm * 32 + mt * 16 + (lane & 15);
                int kc = ks * 2 + (lane >> 4);
                uint32_t o = p * STG + (uint32_t)(r * 80) + (uint32_t)(kc * 16);
                ldsm_x4(ahf[mt], sb + o);
                ldsm_x4(alf[mt], sb + A_B + o);
            }
            uint32_t bhf[NT][2], blf[NT][2];
#pragma unroll
            for (int np = 0; np < NT / 2; np++) {
                int n = wn * WARP_N + np * 16 + (lane & 7) + ((lane >> 4) << 3);
                int kc = ks * 2 + ((lane >> 3) & 1);
                uint32_t o = p * STG + 2 * A_B + (uint32_t)(n * 80) + (uint32_t)(kc * 16);
                uint32_t t4[4];
                ldsm_x4(t4, sb + o);
                bhf[np * 2][0] = t4[0]; bhf[np * 2][1] = t4[1];
                bhf[np * 2 + 1][0] = t4[2]; bhf[np * 2 + 1][1] = t4[3];
                ldsm_x4(t4, sb + B_B + o);
                blf[np * 2][0] = t4[0]; blf[np * 2][1] = t4[1];
                blf[np * 2 + 1][0] = t4[2]; blf[np * 2 + 1][1] = t4[3];
            }
#pragma unroll
            for (int mt = 0; mt < 2; mt++)
#pragma unroll
                for (int nt = 0; nt < NT; nt++) {
                    mma_bf16(acc[mt][nt], ahf[mt], bhf[nt]);
                    mma_bf16(acc[mt][nt], alf[mt], bhf[nt]);
                    mma_bf16(acc[mt][nt], ahf[mt], blf[nt]);
                }
        }
    };

    loadB(0, 0);
    if (SPLIT_A) { ldgA(0); stsA(0); }
    else loadA_cp(0, 0);
    CP_COMMIT();
    CP_WAIT0();
    __syncthreads();

    int p = 0;
#pragma unroll
    for (int s = 0; s < 8; s++) {
        const int sn = s + 1;
        if (sn < 8) {
            loadB(sn, p ^ 1);
            if (SPLIT_A && sn < 4) ldgA(sn);
            else loadA_cp(sn, p ^ 1);
            CP_COMMIT();
        }
        compute(p);
        if (sn < 8) {
            if (SPLIT_A && sn < 4) stsA(p ^ 1);
            CP_WAIT0();
            __syncthreads();
            p ^= 1;
        }
    }

    const int g = lane >> 2, t = lane & 3;
#pragma unroll
    for (int mt = 0; mt < 2; mt++) {
        int r0 = row0 + wm * 32 + mt * 16 + g;
        int r1 = r0 + 8;
#pragma unroll
        for (int nt = 0; nt < NT; nt++) {
            int col = wn * WARP_N + nt * 8 + 2 * t;
            float b0 = __ldg(bias + col), b1 = __ldg(bias + col + 1);
            float c0 = acc[mt][nt][0] + b0, c1 = acc[mt][nt][1] + b1;
            float c2 = acc[mt][nt][2] + b0, c3 = acc[mt][nt][3] + b1;
            if (RELU) {
                c0 = fmaxf(c0, 0.f); c1 = fmaxf(c1, 0.f);
                c2 = fmaxf(c2, 0.f); c3 = fmaxf(c3, 0.f);
            }
            if (SPLIT_OUT) {
                __nv_bfloat16 h0, h1, l0, l1;
                if (r0 < NN) {
                    split1(c0, h0, l0); split1(c1, h1, l1);
                    size_t o = ((size_t)r0 << 7) + col;
                    *(uint32_t*)(ohi + o) = pack2(h0, h1);
                    *(uint32_t*)(olo + o) = pack2(l0, l1);
                }
                if (r1 < NN) {
                    split1(c2, h0, l0); split1(c3, h1, l1);
                    size_t o = ((size_t)r1 << 7) + col;
                    *(uint32_t*)(ohi + o) = pack2(h0, h1);
                    *(uint32_t*)(olo + o) = pack2(l0, l1);
                }
            } else {
                if (r0 < NN) *(float2*)(outf + (size_t)r0 * DOUT + col) = make_float2(c0, c1);
                if (r1 < NN) *(float2*)(outf + (size_t)r1 * DOUT + col) = make_float2(c2, c3);
            }
        }
    }
}

// ---------------------------------------------------------------------------

extern "C" void kernel_launch(void* const* d_in, const int* in_sizes, int n_in,
                              void* d_out, int out_size) {
    const float* x   = (const float*)d_in[0];
    const int* esrc  = (const int*)d_in[1];
    const int* edst  = (const int*)d_in[2];
    const float* Ws1 = (const float*)d_in[3];
    const float* Wn1 = (const float*)d_in[4];
    const float* b1  = (const float*)d_in[5];
    const float* Ws2 = (const float*)d_in[6];
    const float* Wn2 = (const float*)d_in[7];
    const float* b2  = (const float*)d_in[8];
    const float* Ws3 = (const float*)d_in[9];
    const float* Wn3 = (const float*)d_in[10];
    const float* b3  = (const float*)d_in[11];
    float* out = (float*)d_out;

    __nv_bfloat16 *s0hi, *s0lo, *s1hi, *s1lo, *aghi, *aglo, *whi, *wlo;
    cudaGetSymbolAddress((void**)&s0hi, g_s0hi);
    cudaGetSymbolAddress((void**)&s0lo, g_s0lo);
    cudaGetSymbolAddress((void**)&s1hi, g_s1hi);
    cudaGetSymbolAddress((void**)&s1lo, g_s1lo);
    cudaGetSymbolAddress((void**)&aghi, g_agghi);
    cudaGetSymbolAddress((void**)&aglo, g_agglo);
    cudaGetSymbolAddress((void**)&whi, g_whi);
    cudaGetSymbolAddress((void**)&wlo, g_wlo);

    const int SMEM128 = 2 * (2 * 128 * 80 + 2 * 128 * 80);  // 81920
    const int SMEM64  = 2 * (2 * 128 * 80 + 2 * 64 * 80);   // 61440
    cudaFuncSetAttribute(k_gemm_mma<128, true, true, true>,
                         cudaFuncAttributeMaxDynamicSharedMemorySize, SMEM128);
    cudaFuncSetAttribute(k_gemm_mma<128, true, true, false>,
                         cudaFuncAttributeMaxDynamicSharedMemorySize, SMEM128);
    cudaFuncSetAttribute(k_gemm_mma<64, false, false, false>,
                         cudaFuncAttributeMaxDynamicSharedMemorySize, SMEM64);

    const int TB = 256;
    const int gridN = (NN + TB - 1) / TB;
    const int gridE = (NE + TB - 1) / TB;
    const int gridW = (NN * 32 + TB - 1) / TB;
    const int gridM = (NN + 127) / 128;  // 782

    // CSR build (4 launches)
    k_zero<<<gridN, TB>>>();
    k_hist<<<gridE, TB>>>(edst);
    k_scan<<<NB_SCAN, 1024>>>();
    k_scatter<<<gridE, TB>>>(esrc, edst);

    // weights split (tiny)
    k_conv_w<<<(NWE / 4 + 127) / 128, 128>>>(Ws1, Wn1, Ws2, Wn2, Ws3, Wn3);

    // Layer 1 (launch #5 = k_agg_f32 -> ncu capture target)
    k_agg_f32<<<gridW, TB>>>(x, aghi, aglo);
    k_gemm_mma<128, true, true, true><<<gridM, 256, SMEM128>>>(
        x, nullptr, nullptr, aghi, aglo,
        whi + WS1, wlo + WS1, whi + WN1, wlo + WN1, b1,
        nullptr, s1hi, s1lo);

    // Layer 2
    k_agg_split<<<gridW, TB>>>(s1hi, s1lo, aghi, aglo);
    k_gemm_mma<128, true, true, false><<<gridM, 256, SMEM128>>>(
        nullptr, s1hi, s1lo, aghi, aglo,
        whi + WS2, wlo + WS2, whi + WN2, wlo + WN2, b2,
        nullptr, s0hi, s0lo);

    // Layer 3 (fp32 out)
    k_agg_split<<<gridW, TB>>>(s0hi, s0lo, aghi, aglo);
    k_gemm_mma<64, false, false, false><<<gridM, 256, SMEM64>>>(
        nullptr, s0hi, s0lo, aghi, aglo,
        whi + WS3, wlo + WS3, whi + WN3, wlo + WN3, b3,
        out, nullptr, nullptr);
}